// round 2
// baseline (speedup 1.0000x reference)
#include <cuda_runtime.h>
#include <cuda_bf16.h>
#include <math.h>

// ---------------------------------------------------------------------------
// ArticulatoryVQTokenizer fused kernel (fp32), XLA-order-matched arithmetic.
// N = 131072 tokens. Outputs (float32, concatenated):
//   [0, 1835008)            reconstructed (16,8192,14)
//   [1835008, 1966080)      indices (16,8192) as float
//   [1966080]               commit_loss
//   [1966081]               perplexity
// ---------------------------------------------------------------------------

#define TPB        128
#define TILE       128
#define NTOK       131072
#define NTILES     (NTOK / TILE)     // 1024
#define GRID_A     148
#define HPAD       133
#define KCODES     512
#define CHUNK      64
#define NCHUNK     (KCODES / CHUNK)  // 8
#define LATENT     64
#define HID        128
#define INDIM      14

#define OUT_IDX_OFF   1835008
#define OUT_COMMIT    1966080
#define OUT_PERP      1966081

// smem layout (floats)
#define OFF_W1T   0                      // 128*16
#define OFF_W2    (OFF_W1T + 2048)       // 128*64
#define OFF_DW1T  (OFF_W2 + 8192)        // 128*64
#define OFF_DW2T  (OFF_DW1T + 8192)      // 128*16
#define OFF_EB1   (OFF_DW2T + 2048)      // 128
#define OFF_LN1G  (OFF_EB1 + 128)
#define OFF_LN1B  (OFF_LN1G + 128)
#define OFF_B2    (OFF_LN1B + 128)       // 64
#define OFF_DB1   (OFF_B2 + 64)          // 128
#define OFF_LN2G  (OFF_DB1 + 128)
#define OFF_LN2B  (OFF_LN2G + 128)
#define OFF_DB2   (OFF_LN2B + 128)       // 16
#define OFF_CC    (OFF_DB2 + 16)         // 64
#define OFF_RED   (OFF_CC + 64)          // 128
#define OFF_H     (OFF_RED + 128)        // 128*133 = 17024
#define OFF_C     (OFF_H + 17024)        // 64*64 = 4096
#define OFF_HIST  (OFF_C + 4096)         // 512 ints
#define SMEM_FLOATS (OFF_HIST + 512)
#define SMEM_BYTES  (SMEM_FLOATS * 4)    // 172608 bytes

__device__ int   g_counts[KCODES];
__device__ float g_cc[KCODES];        // ||c||^2, square-then-add, sequential
__device__ float g_commit[GRID_A];

// gelu exact, matching jax: 0.5 * x * (1 + erf(x / sqrt(2)))
__device__ __forceinline__ float gelu_exact(float t) {
    float u = __fdiv_rn(t, 1.41421356237309515f);
    float e = erff(u);
    return __fmul_rn(__fmul_rn(0.5f, t), __fadd_rn(1.0f, e));
}

// ---------------------------------------------------------------------------
__global__ void vq_prep_kernel(const float* __restrict__ cb) {
    int t = threadIdx.x;  // 512 threads
    g_counts[t] = 0;
    const float* p = cb + t * LATENT;
    // sequential square-then-add (matches jnp.sum(codebook*codebook, -1))
    float acc = 0.f;
#pragma unroll
    for (int k = 0; k < LATENT; k++) {
        float c = __ldg(p + k);
        acc = __fadd_rn(acc, __fmul_rn(c, c));
    }
    g_cc[t] = acc;
}

// ---------------------------------------------------------------------------
__global__ void __launch_bounds__(TPB, 1)
vq_main_kernel(const float* __restrict__ X,
               const float* __restrict__ EW1, const float* __restrict__ EB1,
               const float* __restrict__ L1G, const float* __restrict__ L1B,
               const float* __restrict__ EW2, const float* __restrict__ EB2,
               const float* __restrict__ CB,
               const float* __restrict__ DW1, const float* __restrict__ DB1,
               const float* __restrict__ L2G, const float* __restrict__ L2B,
               const float* __restrict__ DW2, const float* __restrict__ DB2,
               float* __restrict__ out) {
    extern __shared__ float sm[];
    float* sW1T  = sm + OFF_W1T;
    float* sW2   = sm + OFF_W2;
    float* sDW1T = sm + OFF_DW1T;
    float* sDW2T = sm + OFF_DW2T;
    float* sEB1  = sm + OFF_EB1;
    float* sL1G  = sm + OFF_LN1G;
    float* sL1B  = sm + OFF_LN1B;
    float* sB2   = sm + OFF_B2;
    float* sDB1  = sm + OFF_DB1;
    float* sL2G  = sm + OFF_LN2G;
    float* sL2B  = sm + OFF_LN2B;
    float* sDB2  = sm + OFF_DB2;
    float* sCc   = sm + OFF_CC;
    float* sRed  = sm + OFF_RED;
    float* sH    = sm + OFF_H;
    float* sC    = sm + OFF_C;
    int*   sHist = (int*)(sm + OFF_HIST);

    const int tid = threadIdx.x;

    // ---- one-time block init: transpose/copy weights into smem ----
    for (int i = tid; i < INDIM * HID; i += TPB) {            // enc_w1 (14,128) -> [j][i16]
        int r = i / HID, c = i % HID;
        sW1T[c * 16 + r] = EW1[i];
    }
    for (int i = tid; i < HID; i += TPB) { sW1T[i * 16 + 14] = 0.f; sW1T[i * 16 + 15] = 0.f; }
    for (int i = tid; i < HID * LATENT; i += TPB) sW2[i] = EW2[i];       // (128,64) as-is
    for (int i = tid; i < LATENT * HID; i += TPB) {           // dec_w1 (64,128) -> [j][k]
        int r = i / HID, c = i % HID;
        sDW1T[c * LATENT + r] = DW1[i];
    }
    for (int i = tid; i < HID * INDIM; i += TPB) {            // dec_w2 (128,14) -> [j][i16]
        int r = i / INDIM, c = i % INDIM;
        sDW2T[r * 16 + c] = DW2[i];
    }
    for (int i = tid; i < HID; i += TPB) { sDW2T[i * 16 + 14] = 0.f; sDW2T[i * 16 + 15] = 0.f; }
    for (int i = tid; i < HID; i += TPB) {
        sEB1[i] = EB1[i]; sL1G[i] = L1G[i]; sL1B[i] = L1B[i];
        sDB1[i] = DB1[i]; sL2G[i] = L2G[i]; sL2B[i] = L2B[i];
    }
    for (int i = tid; i < LATENT; i += TPB) sB2[i] = EB2[i];
    for (int i = tid; i < 16; i += TPB) sDB2[i] = (i < INDIM) ? DB2[i] : 0.f;
    for (int i = tid; i < KCODES; i += TPB) sHist[i] = 0;
    __syncthreads();

    float commitAcc = 0.f;
    float* myH = sH + tid * HPAD;
    const float inv128 = 0.0078125f;

    for (int tile = blockIdx.x; tile < NTILES; tile += gridDim.x) {
        const int tok = tile * TILE + tid;

        // ---- load x ----
        float xr[16];
        const float* xp = X + (size_t)tok * INDIM;
#pragma unroll
        for (int i = 0; i < INDIM; i++) xr[i] = __ldg(xp + i);
        xr[14] = 0.f; xr[15] = 0.f;

        // ---- encoder stage 1: h1 = x @ W1 (sequential-k fma) + b1, then mean ----
        float sum = 0.f;
#pragma unroll 4
        for (int j = 0; j < HID; j++) {
            const float* w = sW1T + j * 16;
            float acc = 0.f;
#pragma unroll
            for (int i = 0; i < INDIM; i++) acc = fmaf(xr[i], w[i], acc);
            float a = __fadd_rn(acc, sEB1[j]);
            sum = __fadd_rn(sum, a);
            myH[j] = a;
        }
        float mu = __fmul_rn(sum, inv128);
        // two-pass variance: mean((h - mu)^2)
        float vs = 0.f;
#pragma unroll 4
        for (int j = 0; j < HID; j++) {
            float d = __fsub_rn(myH[j], mu);
            vs = __fadd_rn(vs, __fmul_rn(d, d));
        }
        float var = __fmul_rn(vs, inv128);
        float rs = __fdiv_rn(1.0f, sqrtf(__fadd_rn(var, 1e-5f)));

        // ---- encoder stage 2: z = GELU(LN(h1)) @ W2 (seq-j fma) + b2 ----
        float z[LATENT];
#pragma unroll
        for (int k = 0; k < LATENT; k++) z[k] = 0.f;
#pragma unroll 2
        for (int j = 0; j < HID; j++) {
            float h = myH[j];
            float t = __fadd_rn(__fmul_rn(__fmul_rn(__fsub_rn(h, mu), rs), sL1G[j]), sL1B[j]);
            float g = gelu_exact(t);
            const float* w = sW2 + j * LATENT;
#pragma unroll
            for (int k = 0; k < LATENT; k++) z[k] = fmaf(g, w[k], z[k]);
        }
#pragma unroll
        for (int k = 0; k < LATENT; k++) z[k] = __fadd_rn(z[k], sB2[k]);

        // zz = sum(z*z): square-then-add, sequential
        float zz = 0.f;
#pragma unroll
        for (int k = 0; k < LATENT; k++) zz = __fadd_rn(zz, __fmul_rn(z[k], z[k]));

        // ---- VQ: d2 = (zz - 2*dot) + cc, ascending index, strict < argmin ----
        float best = 3.4e38f;
        int bidx = 0;
        for (int ch = 0; ch < NCHUNK; ch++) {
            __syncthreads();
            const float4* src = (const float4*)(CB + (size_t)ch * CHUNK * LATENT);
            float4* dst = (float4*)sC;
            for (int i = tid; i < CHUNK * LATENT / 4; i += TPB) dst[i] = __ldg(src + i);
            if (tid < CHUNK) sCc[tid] = g_cc[ch * CHUNK + tid];
            __syncthreads();
#pragma unroll 4
            for (int c = 0; c < CHUNK; c++) {
                const float* cw = sC + c * LATENT;
                float acc = 0.f;
#pragma unroll
                for (int k = 0; k < LATENT; k++) acc = fmaf(z[k], cw[k], acc);
                float d2 = __fadd_rn(__fsub_rn(zz, __fmul_rn(2.0f, acc)), sCc[c]);
                if (d2 < best) { best = d2; bidx = ch * CHUNK + c; }
            }
        }
        atomicAdd(&sHist[bidx], 1);
        out[OUT_IDX_OFF + tok] = (float)bidx;

        // ---- fetch q = codebook[bidx]; q_st = z + (q - z) (fp round-trip!) ----
        float qst[LATENT];
        float closs = 0.f;
        const float4* qp = (const float4*)(CB + (size_t)bidx * LATENT);
#pragma unroll
        for (int k4 = 0; k4 < 16; k4++) {
            float4 f = __ldg(qp + k4);
            float qv[4] = {f.x, f.y, f.z, f.w};
#pragma unroll
            for (int u = 0; u < 4; u++) {
                int k = 4 * k4 + u;
                float dqz = __fsub_rn(qv[u], z[k]);
                closs = __fadd_rn(closs, __fmul_rn(dqz, dqz));
                qst[k] = __fadd_rn(z[k], dqz);
            }
        }
        commitAcc += closs;

        // ---- decoder stage 1: h2 = q_st @ dW1 (seq-k fma) + db1 ----
        sum = 0.f;
#pragma unroll 2
        for (int j = 0; j < HID; j++) {
            const float* w = sDW1T + j * LATENT;
            float acc = 0.f;
#pragma unroll
            for (int k = 0; k < LATENT; k++) acc = fmaf(qst[k], w[k], acc);
            float a = __fadd_rn(acc, sDB1[j]);
            sum = __fadd_rn(sum, a);
            myH[j] = a;
        }
        float mu2 = __fmul_rn(sum, inv128);
        float vs2 = 0.f;
#pragma unroll 4
        for (int j = 0; j < HID; j++) {
            float d = __fsub_rn(myH[j], mu2);
            vs2 = __fadd_rn(vs2, __fmul_rn(d, d));
        }
        float var2 = __fmul_rn(vs2, inv128);
        float rs2 = __fdiv_rn(1.0f, sqrtf(__fadd_rn(var2, 1e-5f)));

        // ---- decoder stage 2: out = GELU(LN(h2)) @ dW2 (seq-j fma) + db2 ----
        float o[16];
#pragma unroll
        for (int i = 0; i < 16; i++) o[i] = 0.f;
#pragma unroll 2
        for (int j = 0; j < HID; j++) {
            float h = myH[j];
            float t = __fadd_rn(__fmul_rn(__fmul_rn(__fsub_rn(h, mu2), rs2), sL2G[j]), sL2B[j]);
            float g = gelu_exact(t);
            const float* w = sDW2T + j * 16;
#pragma unroll
            for (int i = 0; i < 14; i++) o[i] = fmaf(g, w[i], o[i]);
        }
        float* op = out + (size_t)tok * INDIM;
#pragma unroll
        for (int i = 0; i < INDIM; i++) op[i] = __fadd_rn(o[i], sDB2[i]);
    }

    // ---- deterministic block reductions ----
    __syncthreads();
    sRed[tid] = commitAcc;
    __syncthreads();
#pragma unroll
    for (int s = 64; s > 0; s >>= 1) {
        if (tid < s) sRed[tid] += sRed[tid + s];
        __syncthreads();
    }
    if (tid == 0) g_commit[blockIdx.x] = sRed[0];
    for (int i = tid; i < KCODES; i += TPB) {
        int c = sHist[i];
        if (c) atomicAdd(&g_counts[i], c);
    }
}

// ---------------------------------------------------------------------------
__global__ void vq_finalize_kernel(float* __restrict__ out) {
    __shared__ float red[KCODES];
    int t = threadIdx.x;  // 512 threads
    float p = (float)g_counts[t] * (1.0f / (float)NTOK);
    red[t] = p * logf(p + 1e-10f);
    __syncthreads();
#pragma unroll
    for (int s = 256; s > 0; s >>= 1) {
        if (t < s) red[t] += red[t + s];
        __syncthreads();
    }
    if (t == 0) {
        float s = 0.f;
        for (int i = 0; i < GRID_A; i++) s += g_commit[i];
        out[OUT_COMMIT] = 0.25f * (s / ((float)NTOK * (float)LATENT));
        out[OUT_PERP] = expf(-red[0]);
    }
}

// ---------------------------------------------------------------------------
extern "C" void kernel_launch(void* const* d_in, const int* in_sizes, int n_in,
                              void* d_out, int out_size) {
    const float* x    = (const float*)d_in[0];
    const float* ew1  = (const float*)d_in[1];
    const float* eb1  = (const float*)d_in[2];
    const float* l1g  = (const float*)d_in[3];
    const float* l1b  = (const float*)d_in[4];
    const float* ew2  = (const float*)d_in[5];
    const float* eb2  = (const float*)d_in[6];
    const float* cb   = (const float*)d_in[7];
    const float* dw1  = (const float*)d_in[8];
    const float* db1  = (const float*)d_in[9];
    const float* l2g  = (const float*)d_in[10];
    const float* l2b  = (const float*)d_in[11];
    const float* dw2  = (const float*)d_in[12];
    const float* db2  = (const float*)d_in[13];
    float* out = (float*)d_out;

    cudaFuncSetAttribute(vq_main_kernel,
                         cudaFuncAttributeMaxDynamicSharedMemorySize, SMEM_BYTES);

    vq_prep_kernel<<<1, KCODES>>>(cb);
    vq_main_kernel<<<GRID_A, TPB, SMEM_BYTES>>>(
        x, ew1, eb1, l1g, l1b, ew2, eb2, cb,
        dw1, db1, l2g, l2b, dw2, db2, out);
    vq_finalize_kernel<<<1, KCODES>>>(out);
}

// round 3
// speedup vs baseline: 1.2394x; 1.2394x over previous
#include <cuda_runtime.h>
#include <math.h>

// ---------------------------------------------------------------------------
// ArticulatoryVQTokenizer single fused kernel (fp32), XLA-order-matched.
// N = 131072 tokens. Outputs (float32, concatenated):
//   [0, 1835008)            reconstructed (16,8192,14)
//   [1835008, 1966080)      indices (16,8192) as float
//   [1966080]               commit_loss
//   [1966081]               perplexity
// ---------------------------------------------------------------------------

#define TPB        256
#define NTOK       131072
#define NTASK      (NTOK / 32)       // 4096 warp-tasks (32 tokens each)
#define GRID_A     148
#define NPAIR      (GRID_A * 4)      // 592 SMSP-pairs
#define KCODES     512
#define NCHUNK     128               // 4 codes per chunk
#define LATENT     64
#define HID        128
#define INDIM      14

#define OUT_IDX_OFF   1835008
#define OUT_COMMIT    1966080
#define OUT_PERP      1966081

// smem layout (float offsets)
#define OFF_W1T   0                      // 128*16  = 2048
#define OFF_W2    2048                   // 128*64  = 8192
#define OFF_DW1T  10240                  // 128*64  = 8192
#define OFF_DW2T  18432                  // 128*16  = 2048
#define OFF_EB1   20480                  // 128
#define OFF_LN1G  20608                  // 128
#define OFF_LN1B  20736                  // 128
#define OFF_B2    20864                  // 64
#define OFF_DB1   20928                  // 128
#define OFF_LN2G  21056                  // 128
#define OFF_LN2B  21184                  // 128
#define OFF_DB2   21312                  // 16
#define OFF_CC    21328                  // 512
#define OFF_RED   21840                  // 256
#define OFF_HIST  22096                  // 512 ints
#define OFF_CHUNK 22608                  // 8 warps * 256 = 2048
#define OFF_H     24656                  // 128*256 = 32768 (thread-major)
#define SMEM_FLOATS (OFF_H + HID * TPB)  // 57424
#define SMEM_BYTES  (SMEM_FLOATS * 4)    // 229696 bytes

__device__ int          g_counts[KCODES];
__device__ float        g_commit[GRID_A];
__device__ unsigned int g_done = 0;

// gelu exact, matching jax: 0.5 * x * (1 + erf(x / sqrt(2)))
__device__ __forceinline__ float gelu_exact(float t) {
    float u = __fdiv_rn(t, 1.41421356237309515f);
    float e = erff(u);
    return __fmul_rn(__fmul_rn(0.5f, t), __fadd_rn(1.0f, e));
}

// ---------------------------------------------------------------------------
__global__ void __launch_bounds__(TPB, 1)
vq_fused_kernel(const float* __restrict__ X,
                const float* __restrict__ EW1, const float* __restrict__ EB1,
                const float* __restrict__ L1G, const float* __restrict__ L1B,
                const float* __restrict__ EW2, const float* __restrict__ EB2,
                const float* __restrict__ CB,
                const float* __restrict__ DW1, const float* __restrict__ DB1,
                const float* __restrict__ L2G, const float* __restrict__ L2B,
                const float* __restrict__ DW2, const float* __restrict__ DB2,
                float* __restrict__ out) {
    extern __shared__ float sm[];
    float* sW1T  = sm + OFF_W1T;
    float* sW2   = sm + OFF_W2;
    float* sDW1T = sm + OFF_DW1T;
    float* sDW2T = sm + OFF_DW2T;
    float* sEB1  = sm + OFF_EB1;
    float* sL1G  = sm + OFF_LN1G;
    float* sL1B  = sm + OFF_LN1B;
    float* sB2   = sm + OFF_B2;
    float* sDB1  = sm + OFF_DB1;
    float* sL2G  = sm + OFF_LN2G;
    float* sL2B  = sm + OFF_LN2B;
    float* sDB2  = sm + OFF_DB2;
    float* sCc   = sm + OFF_CC;
    float* sRed  = sm + OFF_RED;
    int*   sHist = (int*)(sm + OFF_HIST);

    const int tid  = threadIdx.x;
    const int wid  = tid >> 5;
    const int lane = tid & 31;

    // ---- one-time block init ----
    for (int i = tid; i < INDIM * HID; i += TPB) {            // enc_w1 (14,128) -> [j][i16]
        int r = i / HID, c = i % HID;
        sW1T[c * 16 + r] = EW1[i];
    }
    for (int i = tid; i < HID; i += TPB) { sW1T[i * 16 + 14] = 0.f; sW1T[i * 16 + 15] = 0.f; }
    for (int i = tid; i < HID * LATENT; i += TPB) sW2[i] = EW2[i];       // (128,64) as-is
    for (int i = tid; i < LATENT * HID; i += TPB) {           // dec_w1 (64,128) -> [j][k]
        int r = i / HID, c = i % HID;
        sDW1T[c * LATENT + r] = DW1[i];
    }
    for (int i = tid; i < HID * INDIM; i += TPB) {            // dec_w2 (128,14) -> [j][i16]
        int r = i / INDIM, c = i % INDIM;
        sDW2T[r * 16 + c] = DW2[i];
    }
    for (int i = tid; i < HID; i += TPB) { sDW2T[i * 16 + 14] = 0.f; sDW2T[i * 16 + 15] = 0.f; }
    for (int i = tid; i < HID; i += TPB) {
        sEB1[i] = EB1[i]; sL1G[i] = L1G[i]; sL1B[i] = L1B[i];
        sDB1[i] = DB1[i]; sL2G[i] = L2G[i]; sL2B[i] = L2B[i];
    }
    for (int i = tid; i < LATENT; i += TPB) sB2[i] = EB2[i];
    for (int i = tid; i < 16; i += TPB) sDB2[i] = (i < INDIM) ? DB2[i] : 0.f;
    for (int i = tid; i < KCODES; i += TPB) sHist[i] = 0;
    // cc = ||c||^2, sequential square-then-add (matches jnp.sum(c*c, -1))
    for (int c = tid; c < KCODES; c += TPB) {
        const float* p = CB + c * LATENT;
        float acc = 0.f;
#pragma unroll
        for (int k = 0; k < LATENT; k++) {
            float v = __ldg(p + k);
            acc = __fadd_rn(acc, __fmul_rn(v, v));
        }
        sCc[c] = acc;
    }
    __syncthreads();

    float commitAcc = 0.f;
    const float inv128 = 0.0078125f;
    const float4* CB4 = (const float4*)CB;
    float4* myCh4 = (float4*)(sm + OFF_CHUNK + (size_t)wid * 256);
    const float* myCh = sm + OFF_CHUNK + (size_t)wid * 256;

    // SMSP-pair balanced task assignment: pair = blk*4 + (wid&3), sub = wid>>2
    const int pair = blockIdx.x * 4 + (wid & 3);
    const int sub  = wid >> 2;

    for (int it = sub; ; it += 2) {
        const int task = pair + it * NPAIR;
        if (task >= NTASK) break;
        const int tok = task * 32 + lane;

        // ---- load x ----
        float xr[16];
        const float* xp = X + (size_t)tok * INDIM;
#pragma unroll
        for (int i = 0; i < INDIM; i++) xr[i] = __ldg(xp + i);
        xr[14] = 0.f; xr[15] = 0.f;

        // ---- encoder stage 1: h1 = x @ W1 (sequential-k fma) + b1, then mean ----
        float sum = 0.f;
#pragma unroll 4
        for (int j = 0; j < HID; j++) {
            const float* w = sW1T + j * 16;
            float acc = 0.f;
#pragma unroll
            for (int i = 0; i < INDIM; i++) acc = fmaf(xr[i], w[i], acc);
            float a = __fadd_rn(acc, sEB1[j]);
            sum = __fadd_rn(sum, a);
            sm[OFF_H + j * TPB + tid] = a;
        }
        float mu = __fmul_rn(sum, inv128);
        // two-pass variance: mean((h - mu)^2)
        float vs = 0.f;
#pragma unroll 4
        for (int j = 0; j < HID; j++) {
            float d = __fsub_rn(sm[OFF_H + j * TPB + tid], mu);
            vs = __fadd_rn(vs, __fmul_rn(d, d));
        }
        float var = __fmul_rn(vs, inv128);
        float rs = __fdiv_rn(1.0f, sqrtf(__fadd_rn(var, 1e-5f)));

        // ---- encoder stage 2: z = GELU(LN(h1)) @ W2 (seq-j fma) + b2 ----
        float z[LATENT];
#pragma unroll
        for (int k = 0; k < LATENT; k++) z[k] = 0.f;
#pragma unroll 2
        for (int j = 0; j < HID; j++) {
            float h = sm[OFF_H + j * TPB + tid];
            float t = __fadd_rn(__fmul_rn(__fmul_rn(__fsub_rn(h, mu), rs), sL1G[j]), sL1B[j]);
            float g = gelu_exact(t);
            const float* w = sW2 + j * LATENT;
#pragma unroll
            for (int k = 0; k < LATENT; k++) z[k] = fmaf(g, w[k], z[k]);
        }
#pragma unroll
        for (int k = 0; k < LATENT; k++) z[k] = __fadd_rn(z[k], sB2[k]);

        // zz = sum(z*z): square-then-add, sequential
        float zz = 0.f;
#pragma unroll
        for (int k = 0; k < LATENT; k++) zz = __fadd_rn(zz, __fmul_rn(z[k], z[k]));

        // ---- VQ: per-warp smem chunks of 4 codes, prefetch next via regs ----
        float best = 3.4e38f;
        int bidx = 0;
        {
            float4 pfa = CB4[lane * 2 + 0];
            float4 pfb = CB4[lane * 2 + 1];
            myCh4[lane * 2 + 0] = pfa;
            myCh4[lane * 2 + 1] = pfb;
            __syncwarp();
#pragma unroll 1
            for (int ch = 0; ch < NCHUNK; ch++) {
                if (ch + 1 < NCHUNK) {
                    pfa = CB4[(ch + 1) * 64 + lane * 2 + 0];
                    pfb = CB4[(ch + 1) * 64 + lane * 2 + 1];
                }
#pragma unroll
                for (int c4 = 0; c4 < 4; c4++) {
                    const float* cw = myCh + c4 * LATENT;
                    float acc = 0.f;
#pragma unroll
                    for (int k = 0; k < LATENT; k++) acc = fmaf(z[k], cw[k], acc);
                    float d2 = __fadd_rn(__fsub_rn(zz, __fmul_rn(2.0f, acc)), sCc[ch * 4 + c4]);
                    if (d2 < best) { best = d2; bidx = ch * 4 + c4; }
                }
                __syncwarp();
                if (ch + 1 < NCHUNK) {
                    myCh4[lane * 2 + 0] = pfa;
                    myCh4[lane * 2 + 1] = pfb;
                }
                __syncwarp();
            }
        }
        atomicAdd(&sHist[bidx], 1);
        out[OUT_IDX_OFF + tok] = (float)bidx;

        // ---- q = codebook[bidx]; q_st = z + (q - z); commit partial ----
        float qst[LATENT];
        float closs = 0.f;
        const float4* qp = (const float4*)(CB + (size_t)bidx * LATENT);
#pragma unroll
        for (int k4 = 0; k4 < 16; k4++) {
            float4 f = __ldg(qp + k4);
            float qv[4] = {f.x, f.y, f.z, f.w};
#pragma unroll
            for (int u = 0; u < 4; u++) {
                int k = 4 * k4 + u;
                float dqz = __fsub_rn(qv[u], z[k]);
                closs = __fadd_rn(closs, __fmul_rn(dqz, dqz));
                qst[k] = __fadd_rn(z[k], dqz);
            }
        }
        commitAcc += closs;

        // ---- decoder stage 1: h2 = q_st @ dW1 (seq-k fma) + db1 ----
        sum = 0.f;
#pragma unroll 2
        for (int j = 0; j < HID; j++) {
            const float* w = sDW1T + j * LATENT;
            float acc = 0.f;
#pragma unroll
            for (int k = 0; k < LATENT; k++) acc = fmaf(qst[k], w[k], acc);
            float a = __fadd_rn(acc, sDB1[j]);
            sum = __fadd_rn(sum, a);
            sm[OFF_H + j * TPB + tid] = a;
        }
        float mu2 = __fmul_rn(sum, inv128);
        float vs2 = 0.f;
#pragma unroll 4
        for (int j = 0; j < HID; j++) {
            float d = __fsub_rn(sm[OFF_H + j * TPB + tid], mu2);
            vs2 = __fadd_rn(vs2, __fmul_rn(d, d));
        }
        float var2 = __fmul_rn(vs2, inv128);
        float rs2 = __fdiv_rn(1.0f, sqrtf(__fadd_rn(var2, 1e-5f)));

        // ---- decoder stage 2: out = GELU(LN(h2)) @ dW2 (seq-j fma) + db2 ----
        float o[16];
#pragma unroll
        for (int i = 0; i < 16; i++) o[i] = 0.f;
#pragma unroll 2
        for (int j = 0; j < HID; j++) {
            float h = sm[OFF_H + j * TPB + tid];
            float t = __fadd_rn(__fmul_rn(__fmul_rn(__fsub_rn(h, mu2), rs2), sL2G[j]), sL2B[j]);
            float g = gelu_exact(t);
            const float* w = sDW2T + j * 16;
#pragma unroll
            for (int i = 0; i < 14; i++) o[i] = fmaf(g, w[i], o[i]);
        }
        float* op = out + (size_t)tok * INDIM;
#pragma unroll
        for (int i = 0; i < INDIM; i++) op[i] = __fadd_rn(o[i], sDB2[i]);
    }

    // ---- deterministic block reductions ----
    __syncthreads();
    sRed[tid] = commitAcc;
    __syncthreads();
#pragma unroll
    for (int s = 128; s > 0; s >>= 1) {
        if (tid < s) sRed[tid] += sRed[tid + s];
        __syncthreads();
    }
    if (tid == 0) g_commit[blockIdx.x] = sRed[0];
    for (int i = tid; i < KCODES; i += TPB) {
        int c = sHist[i];
        if (c) atomicAdd(&g_counts[i], c);
    }

    // ---- last-block finalize (fence + ticket) ----
    __threadfence();
    __shared__ unsigned int sTicket;
    if (tid == 0) sTicket = atomicAdd(&g_done, 1u);
    __syncthreads();
    if (sTicket == GRID_A - 1) {
        // entropy terms: thread t handles codes t and t+256
        float p0 = (float)g_counts[tid] * (1.0f / (float)NTOK);
        float p1 = (float)g_counts[tid + 256] * (1.0f / (float)NTOK);
        sRed[tid] = p0 * logf(p0 + 1e-10f) + p1 * logf(p1 + 1e-10f);
        __syncthreads();
#pragma unroll
        for (int s = 128; s > 0; s >>= 1) {
            if (tid < s) sRed[tid] += sRed[tid + s];
            __syncthreads();
        }
        if (tid == 0) {
            float s = 0.f;
            for (int i = 0; i < GRID_A; i++) s += g_commit[i];
            out[OUT_COMMIT] = 0.25f * (s / ((float)NTOK * (float)LATENT));
            out[OUT_PERP] = expf(-sRed[0]);
        }
        __syncthreads();
        // reset globals for next graph replay
        for (int i = tid; i < KCODES; i += TPB) g_counts[i] = 0;
        if (tid == 0) g_done = 0;
    }
}

// ---------------------------------------------------------------------------
extern "C" void kernel_launch(void* const* d_in, const int* in_sizes, int n_in,
                              void* d_out, int out_size) {
    const float* x    = (const float*)d_in[0];
    const float* ew1  = (const float*)d_in[1];
    const float* eb1  = (const float*)d_in[2];
    const float* l1g  = (const float*)d_in[3];
    const float* l1b  = (const float*)d_in[4];
    const float* ew2  = (const float*)d_in[5];
    const float* eb2  = (const float*)d_in[6];
    const float* cb   = (const float*)d_in[7];
    const float* dw1  = (const float*)d_in[8];
    const float* db1  = (const float*)d_in[9];
    const float* l2g  = (const float*)d_in[10];
    const float* l2b  = (const float*)d_in[11];
    const float* dw2  = (const float*)d_in[12];
    const float* db2  = (const float*)d_in[13];
    float* out = (float*)d_out;

    cudaFuncSetAttribute(vq_fused_kernel,
                         cudaFuncAttributeMaxDynamicSharedMemorySize, SMEM_BYTES);

    vq_fused_kernel<<<GRID_A, TPB, SMEM_BYTES>>>(
        x, ew1, eb1, l1g, l1b, ew2, eb2, cb,
        dw1, db1, l2g, l2b, dw2, db2, out);
}

// round 4
// speedup vs baseline: 1.3465x; 1.0864x over previous
#include <cuda_runtime.h>
#include <math.h>

// ---------------------------------------------------------------------------
// ArticulatoryVQTokenizer fused kernel, fp32 with packed f32x2 FMA (sm_100+).
// Bit-exact argmin path vs XLA ordering. Outputs (float32):
//   [0, 1835008)   reconstructed   [1835008, 1966080) indices
//   [1966080] commit_loss          [1966081] perplexity
// ---------------------------------------------------------------------------

#define TPB        256
#define NTOK       131072
#define NTASK      (NTOK / 32)       // 4096 warp-tasks
#define GRID_A     148
#define NPAIR      (GRID_A * 4)      // 592 SMSPs
#define KCODES     512
#define NCHUNK     128               // 4 codes (2 interleaved pairs) per chunk
#define LATENT     64
#define HID        128
#define INDIM      14

#define OUT_IDX_OFF   1835008
#define OUT_COMMIT    1966080
#define OUT_PERP      1966081

// smem layout (float offsets)
#define OFF_W1P   0                      // 64 pairs * 32 = 2048
#define OFF_W2    2048                   // 128*64 = 8192
#define OFF_DW1P  10240                  // 64 pairs * 128 = 8192
#define OFF_DW2T  18432                  // 128*16 = 2048
#define OFF_EB1   20480                  // 128
#define OFF_LN1G  20608
#define OFF_LN1B  20736
#define OFF_B2    20864                  // 64
#define OFF_DB1   20928
#define OFF_LN2G  21056
#define OFF_LN2B  21184
#define OFF_DB2   21312                  // 16
#define OFF_CC    21328                  // 512
#define OFF_HIST  21840                  // 512 ints
#define OFF_CHUNK 22352                  // 8 warps * 256 = 2048 (sRed overlaps)
#define OFF_H     24400                  // 128*256 = 32768 thread-major
#define SMEM_FLOATS (OFF_H + HID * TPB)  // 57168
#define SMEM_BYTES  (SMEM_FLOATS * 4)    // 228672

typedef unsigned long long u64;

__device__ int          g_counts[KCODES];
__device__ float        g_commit[GRID_A];
__device__ unsigned int g_done = 0;
__device__ float        g_cc[KCODES];
__device__ __align__(16) float g_cbi[KCODES * LATENT];  // pair-interleaved codebook

__device__ __forceinline__ u64 pk2(float lo, float hi) {
    u64 r; asm("mov.b64 %0, {%1, %2};" : "=l"(r) : "f"(lo), "f"(hi)); return r;
}
__device__ __forceinline__ void up2(u64 v, float& lo, float& hi) {
    asm("mov.b64 {%0, %1}, %2;" : "=f"(lo), "=f"(hi) : "l"(v));
}
__device__ __forceinline__ u64 f2fma(u64 a, u64 b, u64 c) {
    u64 d; asm("fma.rn.f32x2 %0, %1, %2, %3;" : "=l"(d) : "l"(a), "l"(b), "l"(c));
    return d;
}

// gelu exact, matching jax: 0.5 * x * (1 + erf(x / sqrt(2)))
__device__ __forceinline__ float gelu_exact(float t) {
    float u = __fdiv_rn(t, 1.41421356237309515f);
    float e = erff(u);
    return __fmul_rn(__fmul_rn(0.5f, t), __fadd_rn(1.0f, e));
}

// ---------------------------------------------------------------------------
// prep: pair-interleave codebook + ||c||^2 (sequential square-then-add)
__global__ void vq_prep_kernel(const float* __restrict__ cb) {
    int idx = blockIdx.x * blockDim.x + threadIdx.x;   // 64*512 = 32768
    int c = idx >> 6, k = idx & 63;
    g_cbi[(c >> 1) * 128 + 2 * k + (c & 1)] = cb[idx];
    if (blockIdx.x == 0) {
        int cc = threadIdx.x;
        const float* p = cb + cc * LATENT;
        float acc = 0.f;
#pragma unroll
        for (int kk = 0; kk < LATENT; kk++) {
            float v = __ldg(p + kk);
            acc = __fadd_rn(acc, __fmul_rn(v, v));
        }
        g_cc[cc] = acc;
    }
}

// ---------------------------------------------------------------------------
__global__ void __launch_bounds__(TPB, 1)
vq_fused_kernel(const float* __restrict__ X,
                const float* __restrict__ EW1, const float* __restrict__ EB1,
                const float* __restrict__ L1G, const float* __restrict__ L1B,
                const float* __restrict__ EW2, const float* __restrict__ EB2,
                const float* __restrict__ CB,
                const float* __restrict__ DW1, const float* __restrict__ DB1,
                const float* __restrict__ L2G, const float* __restrict__ L2B,
                const float* __restrict__ DW2, const float* __restrict__ DB2,
                float* __restrict__ out) {
    extern __shared__ float sm[];
    float* sW1P  = sm + OFF_W1P;
    float* sW2   = sm + OFF_W2;
    float* sDW1P = sm + OFF_DW1P;
    float* sDW2T = sm + OFF_DW2T;
    float* sEB1  = sm + OFF_EB1;
    float* sL1G  = sm + OFF_LN1G;
    float* sL1B  = sm + OFF_LN1B;
    float* sB2   = sm + OFF_B2;
    float* sDB1  = sm + OFF_DB1;
    float* sL2G  = sm + OFF_LN2G;
    float* sL2B  = sm + OFF_LN2B;
    float* sDB2  = sm + OFF_DB2;
    float* sCc   = sm + OFF_CC;
    int*   sHist = (int*)(sm + OFF_HIST);

    const int tid  = threadIdx.x;
    const int wid  = tid >> 5;
    const int lane = tid & 31;

    // ---- one-time block init ----
    // enc_w1 (14,128) -> pair-interleaved: sW1P[p*32 + 2i + s] = W1[i][2p+s]
    for (int idx = tid; idx < 64 * 32; idx += TPB) {
        int p = idx >> 5, r = idx & 31, i = r >> 1, s = r & 1;
        sW1P[idx] = (i < INDIM) ? EW1[i * HID + 2 * p + s] : 0.f;
    }
    for (int i = tid; i < HID * LATENT; i += TPB) sW2[i] = EW2[i];   // [j][k]
    // dec_w1 (64,128) -> pair-interleaved: sDW1P[p*128 + 2k + s] = DW1[k][2p+s]
    for (int idx = tid; idx < 64 * 128; idx += TPB) {
        int p = idx >> 7, r = idx & 127, k = r >> 1, s = r & 1;
        sDW1P[idx] = DW1[k * HID + 2 * p + s];
    }
    // dec_w2 (128,14) -> [j][i16] padded
    for (int i = tid; i < HID * INDIM; i += TPB) {
        int r = i / INDIM, c = i % INDIM;
        sDW2T[r * 16 + c] = DW2[i];
    }
    for (int i = tid; i < HID; i += TPB) { sDW2T[i * 16 + 14] = 0.f; sDW2T[i * 16 + 15] = 0.f; }
    for (int i = tid; i < HID; i += TPB) {
        sEB1[i] = EB1[i]; sL1G[i] = L1G[i]; sL1B[i] = L1B[i];
        sDB1[i] = DB1[i]; sL2G[i] = L2G[i]; sL2B[i] = L2B[i];
    }
    for (int i = tid; i < LATENT; i += TPB) sB2[i] = EB2[i];
    for (int i = tid; i < 16; i += TPB) sDB2[i] = (i < INDIM) ? DB2[i] : 0.f;
    for (int i = tid; i < KCODES; i += TPB) { sHist[i] = 0; sCc[i] = g_cc[i]; }
    __syncthreads();

    float commitAcc = 0.f;
    const float inv128 = 0.0078125f;
    const float4* CBI4 = (const float4*)g_cbi;
    float4* myCh4 = (float4*)(sm + OFF_CHUNK + (size_t)wid * 256);
    const float* myCh = sm + OFF_CHUNK + (size_t)wid * 256;

    const int pair = blockIdx.x * 4 + (wid & 3);
    const int sub  = wid >> 2;

    for (int it = sub; ; it += 2) {
        const int task = pair + it * NPAIR;
        if (task >= NTASK) break;
        const int tok = task * 32 + lane;

        // ---- load x, pack duplicated ----
        float xr[INDIM];
        const float* xp = X + (size_t)tok * INDIM;
#pragma unroll
        for (int i = 0; i < INDIM; i++) xr[i] = __ldg(xp + i);
        u64 xd[INDIM];
#pragma unroll
        for (int i = 0; i < INDIM; i++) xd[i] = pk2(xr[i], xr[i]);

        // ---- enc1: h1 = x @ W1 + b1 (per-j sequential-i fma chains) ----
        float sum = 0.f;
#pragma unroll 2
        for (int g = 0; g < 32; g++) {   // 4 j per group (2 pairs)
            const ulonglong2* w0 = (const ulonglong2*)(sW1P + (2 * g) * 32);
            const ulonglong2* w1 = (const ulonglong2*)(sW1P + (2 * g + 1) * 32);
            u64 a0 = 0ull, a1 = 0ull;
#pragma unroll
            for (int ii = 0; ii < 7; ii++) {   // i = 0..13
                ulonglong2 u0 = w0[ii], u1 = w1[ii];
                a0 = f2fma(xd[2 * ii], u0.x, a0);
                a0 = f2fma(xd[2 * ii + 1], u0.y, a0);
                a1 = f2fma(xd[2 * ii], u1.x, a1);
                a1 = f2fma(xd[2 * ii + 1], u1.y, a1);
            }
            float h0, h1, h2, h3;
            up2(a0, h0, h1); up2(a1, h2, h3);
            h0 = __fadd_rn(h0, sEB1[4 * g + 0]);
            h1 = __fadd_rn(h1, sEB1[4 * g + 1]);
            h2 = __fadd_rn(h2, sEB1[4 * g + 2]);
            h3 = __fadd_rn(h3, sEB1[4 * g + 3]);
            sum = __fadd_rn(__fadd_rn(__fadd_rn(__fadd_rn(sum, h0), h1), h2), h3);
            sm[OFF_H + (4 * g + 0) * TPB + tid] = h0;
            sm[OFF_H + (4 * g + 1) * TPB + tid] = h1;
            sm[OFF_H + (4 * g + 2) * TPB + tid] = h2;
            sm[OFF_H + (4 * g + 3) * TPB + tid] = h3;
        }
        float mu = __fmul_rn(sum, inv128);
        float vs = 0.f;
#pragma unroll 4
        for (int j = 0; j < HID; j++) {
            float d = __fsub_rn(sm[OFF_H + j * TPB + tid], mu);
            vs = __fadd_rn(vs, __fmul_rn(d, d));
        }
        float var = __fmul_rn(vs, inv128);
        float rs = __fdiv_rn(1.0f, sqrtf(__fadd_rn(var, 1e-5f)));

        // ---- enc2: z = GELU(LN(h1)) @ W2 + b2, z-lanes packed pairwise ----
        u64 zp[32];
#pragma unroll
        for (int t2 = 0; t2 < 32; t2++) zp[t2] = 0ull;
#pragma unroll 2
        for (int j = 0; j < HID; j++) {
            float h = sm[OFF_H + j * TPB + tid];
            float t = __fadd_rn(__fmul_rn(__fmul_rn(__fsub_rn(h, mu), rs), sL1G[j]), sL1B[j]);
            float gel = gelu_exact(t);
            u64 ag = pk2(gel, gel);
            const ulonglong2* wv = (const ulonglong2*)(sW2 + j * LATENT);
#pragma unroll
            for (int t2 = 0; t2 < 16; t2++) {
                ulonglong2 u = wv[t2];
                zp[2 * t2]     = f2fma(ag, u.x, zp[2 * t2]);
                zp[2 * t2 + 1] = f2fma(ag, u.y, zp[2 * t2 + 1]);
            }
        }
        float z[LATENT];
#pragma unroll
        for (int t2 = 0; t2 < 32; t2++) up2(zp[t2], z[2 * t2], z[2 * t2 + 1]);
#pragma unroll
        for (int k = 0; k < LATENT; k++) z[k] = __fadd_rn(z[k], sB2[k]);

        // zz = sum(z*z), sequential square-then-add
        float zz = 0.f;
#pragma unroll
        for (int k = 0; k < LATENT; k++) zz = __fadd_rn(zz, __fmul_rn(z[k], z[k]));

        // ---- VQ: chunks of 4 codes (2 interleaved pairs), packed dot ----
        float best = 3.4e38f;
        int bidx = 0;
        {
            float4 pfa = CBI4[lane * 2 + 0];
            float4 pfb = CBI4[lane * 2 + 1];
            myCh4[lane * 2 + 0] = pfa;
            myCh4[lane * 2 + 1] = pfb;
            __syncwarp();
#pragma unroll 1
            for (int ch = 0; ch < NCHUNK; ch++) {
                if (ch + 1 < NCHUNK) {
                    pfa = CBI4[(ch + 1) * 64 + lane * 2 + 0];
                    pfb = CBI4[(ch + 1) * 64 + lane * 2 + 1];
                }
                const ulonglong2* b0 = (const ulonglong2*)(myCh);
                const ulonglong2* b1 = (const ulonglong2*)(myCh + 128);
                u64 ac0 = 0ull, ac1 = 0ull;
#pragma unroll
                for (int kk = 0; kk < 32; kk++) {
                    ulonglong2 u0 = b0[kk];
                    ulonglong2 u1 = b1[kk];
                    u64 a0 = pk2(z[2 * kk], z[2 * kk]);
                    u64 a1 = pk2(z[2 * kk + 1], z[2 * kk + 1]);
                    ac0 = f2fma(a0, u0.x, ac0);
                    ac0 = f2fma(a1, u0.y, ac0);
                    ac1 = f2fma(a0, u1.x, ac1);
                    ac1 = f2fma(a1, u1.y, ac1);
                }
                float d0, d1, d2v, d3;
                up2(ac0, d0, d1); up2(ac1, d2v, d3);
                float e0 = __fadd_rn(__fsub_rn(zz, __fmul_rn(2.0f, d0)),  sCc[ch * 4 + 0]);
                float e1 = __fadd_rn(__fsub_rn(zz, __fmul_rn(2.0f, d1)),  sCc[ch * 4 + 1]);
                float e2 = __fadd_rn(__fsub_rn(zz, __fmul_rn(2.0f, d2v)), sCc[ch * 4 + 2]);
                float e3 = __fadd_rn(__fsub_rn(zz, __fmul_rn(2.0f, d3)),  sCc[ch * 4 + 3]);
                if (e0 < best) { best = e0; bidx = ch * 4 + 0; }
                if (e1 < best) { best = e1; bidx = ch * 4 + 1; }
                if (e2 < best) { best = e2; bidx = ch * 4 + 2; }
                if (e3 < best) { best = e3; bidx = ch * 4 + 3; }
                __syncwarp();
                if (ch + 1 < NCHUNK) {
                    myCh4[lane * 2 + 0] = pfa;
                    myCh4[lane * 2 + 1] = pfb;
                }
                __syncwarp();
            }
        }
        atomicAdd(&sHist[bidx], 1);
        out[OUT_IDX_OFF + tok] = (float)bidx;

        // ---- q = CB[bidx]; q_st = z + (q - z); commit partial ----
        float qst[LATENT];
        float closs = 0.f;
        const float4* qp = (const float4*)(CB + (size_t)bidx * LATENT);
#pragma unroll
        for (int k4 = 0; k4 < 16; k4++) {
            float4 f = __ldg(qp + k4);
            float qv[4] = {f.x, f.y, f.z, f.w};
#pragma unroll
            for (int u = 0; u < 4; u++) {
                int k = 4 * k4 + u;
                float dqz = __fsub_rn(qv[u], z[k]);
                closs = __fadd_rn(closs, __fmul_rn(dqz, dqz));
                qst[k] = __fadd_rn(z[k], dqz);
            }
        }
        commitAcc += closs;

        // ---- dec1: h2 = q_st @ dW1 + db1 (per-j sequential-k chains) ----
        sum = 0.f;
#pragma unroll 1
        for (int g = 0; g < 32; g++) {   // 4 j per group
            const ulonglong2* w0 = (const ulonglong2*)(sDW1P + (2 * g) * 128);
            const ulonglong2* w1 = (const ulonglong2*)(sDW1P + (2 * g + 1) * 128);
            u64 a0 = 0ull, a1 = 0ull;
#pragma unroll
            for (int kk = 0; kk < 32; kk++) {
                ulonglong2 u0 = w0[kk], u1 = w1[kk];
                u64 q0 = pk2(qst[2 * kk], qst[2 * kk]);
                u64 q1 = pk2(qst[2 * kk + 1], qst[2 * kk + 1]);
                a0 = f2fma(q0, u0.x, a0);
                a0 = f2fma(q1, u0.y, a0);
                a1 = f2fma(q0, u1.x, a1);
                a1 = f2fma(q1, u1.y, a1);
            }
            float h0, h1, h2, h3;
            up2(a0, h0, h1); up2(a1, h2, h3);
            h0 = __fadd_rn(h0, sDB1[4 * g + 0]);
            h1 = __fadd_rn(h1, sDB1[4 * g + 1]);
            h2 = __fadd_rn(h2, sDB1[4 * g + 2]);
            h3 = __fadd_rn(h3, sDB1[4 * g + 3]);
            sum = __fadd_rn(__fadd_rn(__fadd_rn(__fadd_rn(sum, h0), h1), h2), h3);
            sm[OFF_H + (4 * g + 0) * TPB + tid] = h0;
            sm[OFF_H + (4 * g + 1) * TPB + tid] = h1;
            sm[OFF_H + (4 * g + 2) * TPB + tid] = h2;
            sm[OFF_H + (4 * g + 3) * TPB + tid] = h3;
        }
        float mu2 = __fmul_rn(sum, inv128);
        float vs2 = 0.f;
#pragma unroll 4
        for (int j = 0; j < HID; j++) {
            float d = __fsub_rn(sm[OFF_H + j * TPB + tid], mu2);
            vs2 = __fadd_rn(vs2, __fmul_rn(d, d));
        }
        float var2 = __fmul_rn(vs2, inv128);
        float rs2 = __fdiv_rn(1.0f, sqrtf(__fadd_rn(var2, 1e-5f)));

        // ---- dec2: out = GELU(LN(h2)) @ dW2 + db2 (o-lanes packed) ----
        u64 op[7];
#pragma unroll
        for (int i = 0; i < 7; i++) op[i] = 0ull;
#pragma unroll 2
        for (int j = 0; j < HID; j++) {
            float h = sm[OFF_H + j * TPB + tid];
            float t = __fadd_rn(__fmul_rn(__fmul_rn(__fsub_rn(h, mu2), rs2), sL2G[j]), sL2B[j]);
            float gel = gelu_exact(t);
            u64 ag = pk2(gel, gel);
            const ulonglong2* rv = (const ulonglong2*)(sDW2T + j * 16);
            ulonglong2 u0 = rv[0], u1 = rv[1], u2 = rv[2], u3 = rv[3];
            op[0] = f2fma(ag, u0.x, op[0]);
            op[1] = f2fma(ag, u0.y, op[1]);
            op[2] = f2fma(ag, u1.x, op[2]);
            op[3] = f2fma(ag, u1.y, op[3]);
            op[4] = f2fma(ag, u2.x, op[4]);
            op[5] = f2fma(ag, u2.y, op[5]);
            op[6] = f2fma(ag, u3.x, op[6]);
        }
        float o[14];
#pragma unroll
        for (int i = 0; i < 7; i++) up2(op[i], o[2 * i], o[2 * i + 1]);
        float* opo = out + (size_t)tok * INDIM;
#pragma unroll
        for (int i = 0; i < INDIM; i++) opo[i] = __fadd_rn(o[i], sDB2[i]);
    }

    // ---- deterministic block reductions (sRed overlaps chunk area) ----
    __syncthreads();
    float* sRed = sm + OFF_CHUNK;
    sRed[tid] = commitAcc;
    __syncthreads();
#pragma unroll
    for (int s = 128; s > 0; s >>= 1) {
        if (tid < s) sRed[tid] += sRed[tid + s];
        __syncthreads();
    }
    if (tid == 0) g_commit[blockIdx.x] = sRed[0];
    for (int i = tid; i < KCODES; i += TPB) {
        int c = sHist[i];
        if (c) atomicAdd(&g_counts[i], c);
    }

    // ---- last-block finalize ----
    __threadfence();
    __shared__ unsigned int sTicket;
    if (tid == 0) sTicket = atomicAdd(&g_done, 1u);
    __syncthreads();
    if (sTicket == GRID_A - 1) {
        float p0 = (float)g_counts[tid] * (1.0f / (float)NTOK);
        float p1 = (float)g_counts[tid + 256] * (1.0f / (float)NTOK);
        sRed[tid] = p0 * logf(p0 + 1e-10f) + p1 * logf(p1 + 1e-10f);
        __syncthreads();
#pragma unroll
        for (int s = 128; s > 0; s >>= 1) {
            if (tid < s) sRed[tid] += sRed[tid + s];
            __syncthreads();
        }
        if (tid == 0) {
            float s = 0.f;
            for (int i = 0; i < GRID_A; i++) s += g_commit[i];
            out[OUT_COMMIT] = 0.25f * (s / ((float)NTOK * (float)LATENT));
            out[OUT_PERP] = expf(-sRed[0]);
        }
        __syncthreads();
        for (int i = tid; i < KCODES; i += TPB) g_counts[i] = 0;
        if (tid == 0) g_done = 0;
    }
}

// ---------------------------------------------------------------------------
extern "C" void kernel_launch(void* const* d_in, const int* in_sizes, int n_in,
                              void* d_out, int out_size) {
    const float* x    = (const float*)d_in[0];
    const float* ew1  = (const float*)d_in[1];
    const float* eb1  = (const float*)d_in[2];
    const float* l1g  = (const float*)d_in[3];
    const float* l1b  = (const float*)d_in[4];
    const float* ew2  = (const float*)d_in[5];
    const float* eb2  = (const float*)d_in[6];
    const float* cb   = (const float*)d_in[7];
    const float* dw1  = (const float*)d_in[8];
    const float* db1  = (const float*)d_in[9];
    const float* l2g  = (const float*)d_in[10];
    const float* l2b  = (const float*)d_in[11];
    const float* dw2  = (const float*)d_in[12];
    const float* db2  = (const float*)d_in[13];
    float* out = (float*)d_out;

    cudaFuncSetAttribute(vq_fused_kernel,
                         cudaFuncAttributeMaxDynamicSharedMemorySize, SMEM_BYTES);

    vq_prep_kernel<<<64, 512>>>(cb);
    vq_fused_kernel<<<GRID_A, TPB, SMEM_BYTES>>>(
        x, ew1, eb1, l1g, l1b, ew2, eb2, cb,
        dw1, db1, l2g, l2b, dw2, db2, out);
}

// round 5
// speedup vs baseline: 1.4870x; 1.1044x over previous
#include <cuda_runtime.h>
#include <math.h>

// ---------------------------------------------------------------------------
// ArticulatoryVQTokenizer fused kernel: paired-token VQ (f32x2 lanes = 2 tokens)
// Encoder/decoder per-token, byte-identical arithmetic to passing R4 kernel.
// Outputs (float32): [0,1835008) recon | [1835008,1966080) indices |
//   [1966080] commit_loss | [1966081] perplexity
// ---------------------------------------------------------------------------

#define TPB        256
#define NTOK       131072
#define NTASK2     2048              // 64-token paired warp tasks
#define GRID_A     148
#define KCODES     512
#define LATENT     64
#define HID        128
#define INDIM      14

#define OUT_IDX_OFF   1835008
#define OUT_COMMIT    1966080
#define OUT_PERP      1966081

// smem layout (float offsets)
#define OFF_W1P   0                      // 2048
#define OFF_W2    2048                   // 8192
#define OFF_DW1P  10240                  // 8192
#define OFF_DW2T  18432                  // 2048
#define OFF_EB1   20480                  // 128
#define OFF_LN1G  20608
#define OFF_LN1B  20736
#define OFF_B2    20864                  // 64
#define OFF_DB1   20928
#define OFF_LN2G  21056
#define OFF_LN2B  21184
#define OFF_DB2   21312                  // 16
#define OFF_CC    21328                  // 512
#define OFF_HIST  21840                  // 512 ints
#define OFF_CHUNK 22352                  // 8 warps * 256 = 2048 (finalize red reuses)
#define OFF_H     24400                  // 128*256 thread-major
#define SMEM_FLOATS (OFF_H + HID * TPB)  // 57168
#define SMEM_BYTES  (SMEM_FLOATS * 4)    // 228672

typedef unsigned long long u64;

__device__ int          g_counts[KCODES];
__device__ float        g_taskc[NTASK2];
__device__ unsigned int g_ticket = 0;
__device__ unsigned int g_done = 0;

__device__ __forceinline__ u64 pk2(float lo, float hi) {
    u64 r; asm("mov.b64 %0, {%1, %2};" : "=l"(r) : "f"(lo), "f"(hi)); return r;
}
__device__ __forceinline__ void up2(u64 v, float& lo, float& hi) {
    asm("mov.b64 {%0, %1}, %2;" : "=f"(lo), "=f"(hi) : "l"(v));
}
__device__ __forceinline__ u64 f2fma(u64 a, u64 b, u64 c) {
    u64 d; asm("fma.rn.f32x2 %0, %1, %2, %3;" : "=l"(d) : "l"(a), "l"(b), "l"(c));
    return d;
}

// gelu exact, matching jax: 0.5 * x * (1 + erf(x / sqrt(2)))
__device__ __forceinline__ float gelu_exact(float t) {
    float u = __fdiv_rn(t, 1.41421356237309515f);
    float e = erff(u);
    return __fmul_rn(__fmul_rn(0.5f, t), __fadd_rn(1.0f, e));
}

// ---------------------------------------------------------------------------
// Encoder for one token: z[64] out. Byte-identical to R4 arithmetic.
__device__ __forceinline__ void encode_token(
    float* sm, int tid, const float* __restrict__ X, int tok, float* z)
{
    const float inv128 = 0.0078125f;
    float xr[INDIM];
    const float* xp = X + (size_t)tok * INDIM;
#pragma unroll
    for (int i = 0; i < INDIM; i++) xr[i] = __ldg(xp + i);
    u64 xd[INDIM];
#pragma unroll
    for (int i = 0; i < INDIM; i++) xd[i] = pk2(xr[i], xr[i]);

    float sum = 0.f;
#pragma unroll 2
    for (int g = 0; g < 32; g++) {
        const ulonglong2* w0 = (const ulonglong2*)(sm + OFF_W1P + (2 * g) * 32);
        const ulonglong2* w1 = (const ulonglong2*)(sm + OFF_W1P + (2 * g + 1) * 32);
        u64 a0 = 0ull, a1 = 0ull;
#pragma unroll
        for (int ii = 0; ii < 7; ii++) {
            ulonglong2 u0 = w0[ii], u1 = w1[ii];
            a0 = f2fma(xd[2 * ii], u0.x, a0);
            a0 = f2fma(xd[2 * ii + 1], u0.y, a0);
            a1 = f2fma(xd[2 * ii], u1.x, a1);
            a1 = f2fma(xd[2 * ii + 1], u1.y, a1);
        }
        float h0, h1, h2, h3;
        up2(a0, h0, h1); up2(a1, h2, h3);
        h0 = __fadd_rn(h0, sm[OFF_EB1 + 4 * g + 0]);
        h1 = __fadd_rn(h1, sm[OFF_EB1 + 4 * g + 1]);
        h2 = __fadd_rn(h2, sm[OFF_EB1 + 4 * g + 2]);
        h3 = __fadd_rn(h3, sm[OFF_EB1 + 4 * g + 3]);
        sum = __fadd_rn(__fadd_rn(__fadd_rn(__fadd_rn(sum, h0), h1), h2), h3);
        sm[OFF_H + (4 * g + 0) * TPB + tid] = h0;
        sm[OFF_H + (4 * g + 1) * TPB + tid] = h1;
        sm[OFF_H + (4 * g + 2) * TPB + tid] = h2;
        sm[OFF_H + (4 * g + 3) * TPB + tid] = h3;
    }
    float mu = __fmul_rn(sum, inv128);
    float vs = 0.f;
#pragma unroll 4
    for (int j = 0; j < HID; j++) {
        float d = __fsub_rn(sm[OFF_H + j * TPB + tid], mu);
        vs = __fadd_rn(vs, __fmul_rn(d, d));
    }
    float var = __fmul_rn(vs, inv128);
    float rs = __fdiv_rn(1.0f, sqrtf(__fadd_rn(var, 1e-5f)));

    u64 zp[32];
#pragma unroll
    for (int t2 = 0; t2 < 32; t2++) zp[t2] = 0ull;
#pragma unroll 2
    for (int j = 0; j < HID; j++) {
        float h = sm[OFF_H + j * TPB + tid];
        float t = __fadd_rn(__fmul_rn(__fmul_rn(__fsub_rn(h, mu), rs), sm[OFF_LN1G + j]), sm[OFF_LN1B + j]);
        float gel = gelu_exact(t);
        u64 ag = pk2(gel, gel);
        const ulonglong2* wv = (const ulonglong2*)(sm + OFF_W2 + j * LATENT);
#pragma unroll
        for (int t2 = 0; t2 < 16; t2++) {
            ulonglong2 u = wv[t2];
            zp[2 * t2]     = f2fma(ag, u.x, zp[2 * t2]);
            zp[2 * t2 + 1] = f2fma(ag, u.y, zp[2 * t2 + 1]);
        }
    }
#pragma unroll
    for (int t2 = 0; t2 < 32; t2++) up2(zp[t2], z[2 * t2], z[2 * t2 + 1]);
#pragma unroll
    for (int k = 0; k < LATENT; k++) z[k] = __fadd_rn(z[k], sm[OFF_B2 + k]);
}

// ---------------------------------------------------------------------------
// Decoder for one token; z extracted from ztp halves (HI = 0 lo, 1 hi).
// Returns commit-loss partial. Byte-identical to R4 arithmetic.
template<int HI>
__device__ __forceinline__ float decode_token(
    float* sm, int tid, const float* __restrict__ CB, int tok, int bidx,
    const u64* ztp, float* __restrict__ out)
{
    const float inv128 = 0.0078125f;
    float qst[LATENT];
    float closs = 0.f;
    const float4* qp = (const float4*)(CB + (size_t)bidx * LATENT);
#pragma unroll
    for (int k4 = 0; k4 < 16; k4++) {
        float4 f = __ldg(qp + k4);
        float qv[4] = {f.x, f.y, f.z, f.w};
#pragma unroll
        for (int u = 0; u < 4; u++) {
            int k = 4 * k4 + u;
            float lo, hi; up2(ztp[k], lo, hi);
            float zk = HI ? hi : lo;
            float dqz = __fsub_rn(qv[u], zk);
            closs = __fadd_rn(closs, __fmul_rn(dqz, dqz));
            qst[k] = __fadd_rn(zk, dqz);
        }
    }

    float sum = 0.f;
#pragma unroll 1
    for (int g = 0; g < 32; g++) {
        const ulonglong2* w0 = (const ulonglong2*)(sm + OFF_DW1P + (2 * g) * 128);
        const ulonglong2* w1 = (const ulonglong2*)(sm + OFF_DW1P + (2 * g + 1) * 128);
        u64 a0 = 0ull, a1 = 0ull;
#pragma unroll
        for (int kk = 0; kk < 32; kk++) {
            ulonglong2 u0 = w0[kk], u1 = w1[kk];
            u64 q0 = pk2(qst[2 * kk], qst[2 * kk]);
            u64 q1 = pk2(qst[2 * kk + 1], qst[2 * kk + 1]);
            a0 = f2fma(q0, u0.x, a0);
            a0 = f2fma(q1, u0.y, a0);
            a1 = f2fma(q0, u1.x, a1);
            a1 = f2fma(q1, u1.y, a1);
        }
        float h0, h1, h2, h3;
        up2(a0, h0, h1); up2(a1, h2, h3);
        h0 = __fadd_rn(h0, sm[OFF_DB1 + 4 * g + 0]);
        h1 = __fadd_rn(h1, sm[OFF_DB1 + 4 * g + 1]);
        h2 = __fadd_rn(h2, sm[OFF_DB1 + 4 * g + 2]);
        h3 = __fadd_rn(h3, sm[OFF_DB1 + 4 * g + 3]);
        sum = __fadd_rn(__fadd_rn(__fadd_rn(__fadd_rn(sum, h0), h1), h2), h3);
        sm[OFF_H + (4 * g + 0) * TPB + tid] = h0;
        sm[OFF_H + (4 * g + 1) * TPB + tid] = h1;
        sm[OFF_H + (4 * g + 2) * TPB + tid] = h2;
        sm[OFF_H + (4 * g + 3) * TPB + tid] = h3;
    }
    float mu2 = __fmul_rn(sum, inv128);
    float vs2 = 0.f;
#pragma unroll 4
    for (int j = 0; j < HID; j++) {
        float d = __fsub_rn(sm[OFF_H + j * TPB + tid], mu2);
        vs2 = __fadd_rn(vs2, __fmul_rn(d, d));
    }
    float var2 = __fmul_rn(vs2, inv128);
    float rs2 = __fdiv_rn(1.0f, sqrtf(__fadd_rn(var2, 1e-5f)));

    u64 op[7];
#pragma unroll
    for (int i = 0; i < 7; i++) op[i] = 0ull;
#pragma unroll 2
    for (int j = 0; j < HID; j++) {
        float h = sm[OFF_H + j * TPB + tid];
        float t = __fadd_rn(__fmul_rn(__fmul_rn(__fsub_rn(h, mu2), rs2), sm[OFF_LN2G + j]), sm[OFF_LN2B + j]);
        float gel = gelu_exact(t);
        u64 ag = pk2(gel, gel);
        const ulonglong2* rv = (const ulonglong2*)(sm + OFF_DW2T + j * 16);
        ulonglong2 u0 = rv[0], u1 = rv[1], u2 = rv[2], u3 = rv[3];
        op[0] = f2fma(ag, u0.x, op[0]);
        op[1] = f2fma(ag, u0.y, op[1]);
        op[2] = f2fma(ag, u1.x, op[2]);
        op[3] = f2fma(ag, u1.y, op[3]);
        op[4] = f2fma(ag, u2.x, op[4]);
        op[5] = f2fma(ag, u2.y, op[5]);
        op[6] = f2fma(ag, u3.x, op[6]);
    }
    float o[14];
#pragma unroll
    for (int i = 0; i < 7; i++) up2(op[i], o[2 * i], o[2 * i + 1]);
    float* opo = out + (size_t)tok * INDIM;
#pragma unroll
    for (int i = 0; i < INDIM; i++) opo[i] = __fadd_rn(o[i], sm[OFF_DB2 + i]);
    return closs;
}

// ---------------------------------------------------------------------------
__global__ void __launch_bounds__(TPB, 1)
vq_fused_kernel(const float* __restrict__ X,
                const float* __restrict__ EW1, const float* __restrict__ EB1,
                const float* __restrict__ L1G, const float* __restrict__ L1B,
                const float* __restrict__ EW2, const float* __restrict__ EB2,
                const float* __restrict__ CB,
                const float* __restrict__ DW1, const float* __restrict__ DB1,
                const float* __restrict__ L2G, const float* __restrict__ L2B,
                const float* __restrict__ DW2, const float* __restrict__ DB2,
                float* __restrict__ out) {
    extern __shared__ float sm[];
    int* sHist = (int*)(sm + OFF_HIST);

    const int tid  = threadIdx.x;
    const int wid  = tid >> 5;
    const int lane = tid & 31;

    // ---- one-time block init ----
    for (int idx = tid; idx < 64 * 32; idx += TPB) {   // enc_w1 pair-interleave
        int p = idx >> 5, r = idx & 31, i = r >> 1, s = r & 1;
        sm[OFF_W1P + idx] = (i < INDIM) ? EW1[i * HID + 2 * p + s] : 0.f;
    }
    for (int i = tid; i < HID * LATENT; i += TPB) sm[OFF_W2 + i] = EW2[i];
    for (int idx = tid; idx < 64 * 128; idx += TPB) {  // dec_w1 pair-interleave
        int p = idx >> 7, r = idx & 127, k = r >> 1, s = r & 1;
        sm[OFF_DW1P + idx] = DW1[k * HID + 2 * p + s];
    }
    for (int i = tid; i < HID * INDIM; i += TPB) {     // dec_w2 [j][i16]
        int r = i / INDIM, c = i % INDIM;
        sm[OFF_DW2T + r * 16 + c] = DW2[i];
    }
    for (int i = tid; i < HID; i += TPB) { sm[OFF_DW2T + i * 16 + 14] = 0.f; sm[OFF_DW2T + i * 16 + 15] = 0.f; }
    for (int i = tid; i < HID; i += TPB) {
        sm[OFF_EB1 + i] = EB1[i]; sm[OFF_LN1G + i] = L1G[i]; sm[OFF_LN1B + i] = L1B[i];
        sm[OFF_DB1 + i] = DB1[i]; sm[OFF_LN2G + i] = L2G[i]; sm[OFF_LN2B + i] = L2B[i];
    }
    for (int i = tid; i < LATENT; i += TPB) sm[OFF_B2 + i] = EB2[i];
    for (int i = tid; i < 16; i += TPB) sm[OFF_DB2 + i] = (i < INDIM) ? DB2[i] : 0.f;
    for (int i = tid; i < KCODES; i += TPB) sHist[i] = 0;
    // cc = ||c||^2, sequential square-then-add
    for (int c = tid; c < KCODES; c += TPB) {
        const float* p = CB + c * LATENT;
        float acc = 0.f;
#pragma unroll
        for (int k = 0; k < LATENT; k++) {
            float v = __ldg(p + k);
            acc = __fadd_rn(acc, __fmul_rn(v, v));
        }
        sm[OFF_CC + c] = acc;
    }
    __syncthreads();

    const float4* CB4 = (const float4*)CB;
    float4* myCh4 = (float4*)(sm + OFF_CHUNK + (size_t)wid * 256);
    const float4* ch4 = (const float4*)(sm + OFF_CHUNK + (size_t)wid * 256);

    // ---- dynamic ticket loop: task = 64 tokens (paired lanes) ----
    for (;;) {
        unsigned int t;
        if (lane == 0) t = atomicAdd(&g_ticket, 1u);
        t = __shfl_sync(0xffffffffu, t, 0);
        if (t >= NTASK2) break;
        const int tokA = (int)t * 64 + lane;
        const int tokB = tokA + 32;

        float zA[LATENT];
        encode_token(sm, tid, X, tokA, zA);
        float zzA = 0.f;
#pragma unroll
        for (int k = 0; k < LATENT; k++) zzA = __fadd_rn(zzA, __fmul_rn(zA[k], zA[k]));

        float zB[LATENT];
        encode_token(sm, tid, X, tokB, zB);
        float zzB = 0.f;
#pragma unroll
        for (int k = 0; k < LATENT; k++) zzB = __fadd_rn(zzB, __fmul_rn(zB[k], zB[k]));

        u64 ztp[LATENT];
#pragma unroll
        for (int k = 0; k < LATENT; k++) ztp[k] = pk2(zA[k], zB[k]);

        // ---- paired VQ over 128 chunks of 4 codes ----
        float bestA = 3.4e38f, bestB = 3.4e38f;
        int bidxA = 0, bidxB = 0;
        {
            float4 pfa = CB4[lane * 2 + 0];
            float4 pfb = CB4[lane * 2 + 1];
            myCh4[lane * 2 + 0] = pfa;
            myCh4[lane * 2 + 1] = pfb;
            __syncwarp();
#pragma unroll 1
            for (int ch = 0; ch < 128; ch++) {
                if (ch + 1 < 128) {
                    pfa = CB4[(ch + 1) * 64 + lane * 2 + 0];
                    pfb = CB4[(ch + 1) * 64 + lane * 2 + 1];
                }
                u64 ac0 = 0ull, ac1 = 0ull, ac2 = 0ull, ac3 = 0ull;
#pragma unroll
                for (int kk = 0; kk < 16; kk++) {
                    float4 f0 = ch4[0 * 16 + kk];
                    float4 f1 = ch4[1 * 16 + kk];
                    float4 f2 = ch4[2 * 16 + kk];
                    float4 f3 = ch4[3 * 16 + kk];
                    u64 a0 = ztp[4 * kk + 0], a1 = ztp[4 * kk + 1];
                    u64 a2 = ztp[4 * kk + 2], a3 = ztp[4 * kk + 3];
                    ac0 = f2fma(a0, pk2(f0.x, f0.x), ac0);
                    ac0 = f2fma(a1, pk2(f0.y, f0.y), ac0);
                    ac0 = f2fma(a2, pk2(f0.z, f0.z), ac0);
                    ac0 = f2fma(a3, pk2(f0.w, f0.w), ac0);
                    ac1 = f2fma(a0, pk2(f1.x, f1.x), ac1);
                    ac1 = f2fma(a1, pk2(f1.y, f1.y), ac1);
                    ac1 = f2fma(a2, pk2(f1.z, f1.z), ac1);
                    ac1 = f2fma(a3, pk2(f1.w, f1.w), ac1);
                    ac2 = f2fma(a0, pk2(f2.x, f2.x), ac2);
                    ac2 = f2fma(a1, pk2(f2.y, f2.y), ac2);
                    ac2 = f2fma(a2, pk2(f2.z, f2.z), ac2);
                    ac2 = f2fma(a3, pk2(f2.w, f2.w), ac2);
                    ac3 = f2fma(a0, pk2(f3.x, f3.x), ac3);
                    ac3 = f2fma(a1, pk2(f3.y, f3.y), ac3);
                    ac3 = f2fma(a2, pk2(f3.z, f3.z), ac3);
                    ac3 = f2fma(a3, pk2(f3.w, f3.w), ac3);
                }
                u64 accs[4] = {ac0, ac1, ac2, ac3};
#pragma unroll
                for (int c = 0; c < 4; c++) {
                    float dA, dB; up2(accs[c], dA, dB);
                    float cc = sm[OFF_CC + ch * 4 + c];
                    float eA = __fadd_rn(__fsub_rn(zzA, __fmul_rn(2.0f, dA)), cc);
                    float eB = __fadd_rn(__fsub_rn(zzB, __fmul_rn(2.0f, dB)), cc);
                    if (eA < bestA) { bestA = eA; bidxA = ch * 4 + c; }
                    if (eB < bestB) { bestB = eB; bidxB = ch * 4 + c; }
                }
                __syncwarp();
                if (ch + 1 < 128) {
                    myCh4[lane * 2 + 0] = pfa;
                    myCh4[lane * 2 + 1] = pfb;
                }
                __syncwarp();
            }
        }
        atomicAdd(&sHist[bidxA], 1);
        atomicAdd(&sHist[bidxB], 1);
        out[OUT_IDX_OFF + tokA] = (float)bidxA;
        out[OUT_IDX_OFF + tokB] = (float)bidxB;

        float clA = decode_token<0>(sm, tid, CB, tokA, bidxA, ztp, out);
        float clB = decode_token<1>(sm, tid, CB, tokB, bidxB, ztp, out);

        // per-task deterministic commit partial (fixed shfl tree)
        float cl = __fadd_rn(clA, clB);
#pragma unroll
        for (int s = 16; s > 0; s >>= 1)
            cl = __fadd_rn(cl, __shfl_down_sync(0xffffffffu, cl, s));
        if (lane == 0) g_taskc[t] = cl;
    }

    // ---- merge histogram ----
    __syncthreads();
    for (int i = tid; i < KCODES; i += TPB) {
        int c = sHist[i];
        if (c) atomicAdd(&g_counts[i], c);
    }

    // ---- last-block finalize ----
    __threadfence();
    __shared__ unsigned int sTicket;
    if (tid == 0) sTicket = atomicAdd(&g_done, 1u);
    __syncthreads();
    if (sTicket == GRID_A - 1) {
        float* sRed = sm + OFF_CHUNK;
        // commit: fixed-order reduction over 2048 task partials
        float s8 = 0.f;
#pragma unroll
        for (int j = 0; j < 8; j++) s8 += g_taskc[tid * 8 + j];
        // entropy terms
        float p0 = (float)g_counts[tid] * (1.0f / (float)NTOK);
        float p1 = (float)g_counts[tid + 256] * (1.0f / (float)NTOK);
        float ent = p0 * logf(p0 + 1e-10f) + p1 * logf(p1 + 1e-10f);
        sRed[tid] = s8;
        sRed[256 + tid] = ent;
        __syncthreads();
#pragma unroll
        for (int s = 128; s > 0; s >>= 1) {
            if (tid < s) {
                sRed[tid] += sRed[tid + s];
                sRed[256 + tid] += sRed[256 + tid + s];
            }
            __syncthreads();
        }
        if (tid == 0) {
            out[OUT_COMMIT] = 0.25f * (sRed[0] / ((float)NTOK * (float)LATENT));
            out[OUT_PERP] = expf(-sRed[256]);
        }
        __syncthreads();
        // reset globals for next graph replay
        for (int i = tid; i < KCODES; i += TPB) g_counts[i] = 0;
        if (tid == 0) { g_done = 0; g_ticket = 0; }
    }
}

// ---------------------------------------------------------------------------
extern "C" void kernel_launch(void* const* d_in, const int* in_sizes, int n_in,
                              void* d_out, int out_size) {
    const float* x    = (const float*)d_in[0];
    const float* ew1  = (const float*)d_in[1];
    const float* eb1  = (const float*)d_in[2];
    const float* l1g  = (const float*)d_in[3];
    const float* l1b  = (const float*)d_in[4];
    const float* ew2  = (const float*)d_in[5];
    const float* eb2  = (const float*)d_in[6];
    const float* cb   = (const float*)d_in[7];
    const float* dw1  = (const float*)d_in[8];
    const float* db1  = (const float*)d_in[9];
    const float* l2g  = (const float*)d_in[10];
    const float* l2b  = (const float*)d_in[11];
    const float* dw2  = (const float*)d_in[12];
    const float* db2  = (const float*)d_in[13];
    float* out = (float*)d_out;

    cudaFuncSetAttribute(vq_fused_kernel,
                         cudaFuncAttributeMaxDynamicSharedMemorySize, SMEM_BYTES);

    vq_fused_kernel<<<GRID_A, TPB, SMEM_BYTES>>>(
        x, ew1, eb1, l1g, l1b, ew2, eb2, cb,
        dw1, db1, l2g, l2b, dw2, db2, out);
}